// round 2
// baseline (speedup 1.0000x reference)
#include <cuda_runtime.h>

// D = 16777216 floats per vector; n4 = D/4 float4 elements.
// Output: out[0..D) = x, out[D..D+6) = {ly0·x, ly1·x, ly1·ly0, ly2·x, ly2·ly0, ly2·ly1}
//
// Single-kernel design: each block writes 6 partial sums to __device__ scratch;
// the last block to arrive (atomic ticket + threadfence) reduces all partials
// deterministically and writes the 6-float tail. Counter self-resets -> graph-safe.

#define NBLOCKS 4096
#define NTHREADS 256

__device__ float g_partials[6][NBLOCKS];
__device__ unsigned int g_ticket = 0;

__global__ void __launch_bounds__(NTHREADS)
dlrm_fused_kernel(const float4* __restrict__ xv,
                  const float4* __restrict__ l0v,
                  const float4* __restrict__ l1v,
                  const float4* __restrict__ l2v,
                  float4* __restrict__ outx,
                  float* __restrict__ out_tail,
                  int n4) {
    float s0 = 0.f, s1 = 0.f, s2 = 0.f, s3 = 0.f, s4 = 0.f, s5 = 0.f;

    const int stride = gridDim.x * blockDim.x;
    for (int i = blockIdx.x * blockDim.x + threadIdx.x; i < n4; i += stride) {
        const float4 a = xv[i];
        const float4 b = l0v[i];
        const float4 c = l1v[i];
        const float4 d = l2v[i];
        __stcs(&outx[i], a);  // streaming store: x copy, never re-read

        s0 += b.x * a.x + b.y * a.y + b.z * a.z + b.w * a.w;  // ly0 · x
        s1 += c.x * a.x + c.y * a.y + c.z * a.z + c.w * a.w;  // ly1 · x
        s2 += c.x * b.x + c.y * b.y + c.z * b.z + c.w * b.w;  // ly1 · ly0
        s3 += d.x * a.x + d.y * a.y + d.z * a.z + d.w * a.w;  // ly2 · x
        s4 += d.x * b.x + d.y * b.y + d.z * b.z + d.w * b.w;  // ly2 · ly0
        s5 += d.x * c.x + d.y * c.y + d.z * c.z + d.w * c.w;  // ly2 · ly1
    }

    // Warp-level reduction
    #pragma unroll
    for (int off = 16; off > 0; off >>= 1) {
        s0 += __shfl_down_sync(0xFFFFFFFFu, s0, off);
        s1 += __shfl_down_sync(0xFFFFFFFFu, s1, off);
        s2 += __shfl_down_sync(0xFFFFFFFFu, s2, off);
        s3 += __shfl_down_sync(0xFFFFFFFFu, s3, off);
        s4 += __shfl_down_sync(0xFFFFFFFFu, s4, off);
        s5 += __shfl_down_sync(0xFFFFFFFFu, s5, off);
    }

    __shared__ float smem[6][NTHREADS / 32];
    __shared__ bool s_is_last;
    const int warp = threadIdx.x >> 5;
    const int lane = threadIdx.x & 31;
    if (lane == 0) {
        smem[0][warp] = s0; smem[1][warp] = s1; smem[2][warp] = s2;
        smem[3][warp] = s3; smem[4][warp] = s4; smem[5][warp] = s5;
    }
    __syncthreads();

    // Threads 0..5 write this block's 6 partials to global scratch.
    if (threadIdx.x < 6) {
        float v = 0.f;
        #pragma unroll
        for (int w = 0; w < NTHREADS / 32; w++) v += smem[threadIdx.x][w];
        g_partials[threadIdx.x][blockIdx.x] = v;
    }
    __threadfence();  // make partials visible before taking the ticket
    __syncthreads();

    if (threadIdx.x == 0) {
        unsigned int t = atomicAdd(&g_ticket, 1u);
        s_is_last = (t == gridDim.x - 1);
    }
    __syncthreads();
    if (!s_is_last) return;

    // Last block: deterministic reduction of all NBLOCKS partials per product.
    const int nb = gridDim.x;
    #pragma unroll
    for (int p = 0; p < 6; p++) {
        float v = 0.f;
        for (int j = threadIdx.x; j < nb; j += NTHREADS) v += g_partials[p][j];
        #pragma unroll
        for (int off = 16; off > 0; off >>= 1)
            v += __shfl_down_sync(0xFFFFFFFFu, v, off);
        if (lane == 0) smem[p][warp] = v;
    }
    __syncthreads();
    if (threadIdx.x < 6) {
        float v = 0.f;
        #pragma unroll
        for (int w = 0; w < NTHREADS / 32; w++) v += smem[threadIdx.x][w];
        out_tail[threadIdx.x] = v;
    }
    if (threadIdx.x == 0) g_ticket = 0;  // reset for next graph replay
}

extern "C" void kernel_launch(void* const* d_in, const int* in_sizes, int n_in,
                              void* d_out, int out_size) {
    const float* x  = (const float*)d_in[0];
    const float* l0 = (const float*)d_in[1];
    const float* l1 = (const float*)d_in[2];
    const float* l2 = (const float*)d_in[3];
    float* out = (float*)d_out;

    const int D  = in_sizes[0];   // 16777216
    const int n4 = D / 4;         // 4194304

    int blocks = NBLOCKS;
    const int maxBlocks = (n4 + NTHREADS - 1) / NTHREADS;
    if (blocks > maxBlocks) blocks = maxBlocks;

    dlrm_fused_kernel<<<blocks, NTHREADS>>>(
        (const float4*)x, (const float4*)l0, (const float4*)l1, (const float4*)l2,
        (float4*)out, out + D, n4);
}